// round 2
// baseline (speedup 1.0000x reference)
#include <cuda_runtime.h>

// PartialDataLoss: directional Chamfer (template -> scan), sum of squared NN
// distances below 0.1.
//
// d2[m,n] = |t_m|^2 + |s_n|^2 - 2 t_m.s_n
// min_n d2[m,n] = |t_m|^2 + min_n (|s_n|^2 - 2 t_m.s_n)
//
// Pass 1: pack scan points as (-2x, -2y, -2z, |s|^2) float4, init min table.
// Pass 2: tiled brute force, 3 FFMA + 1 FMNMX per pair, T=4 template points
//         per thread to amortize the one LDS.128 per scan point. Cross-chunk
//         combine via atomicMin on monotone int-mapped float bits.
// Pass 3: add |t_m|^2, threshold, block-reduce sum.

#define BLOCK        256
#define T_PER_THREAD 4
#define SCAN_CHUNKS  64
#define TILE         1024

#define N_MAX 50048
#define M_MAX 8192

__device__ float4 g_pack[N_MAX];
__device__ int    g_minbits[M_MAX];

// Monotone map: float compare == signed int compare after this remap
// (valid for all non-NaN floats).
__device__ __forceinline__ int f2ord(float f) {
    int b = __float_as_int(f);
    return b >= 0 ? b : (b ^ 0x7FFFFFFF);
}
__device__ __forceinline__ float ord2f(int b) {
    return __int_as_float(b >= 0 ? b : (b ^ 0x7FFFFFFF));
}

__global__ void pack_init_kernel(const float* __restrict__ scan, int N, int M) {
    int i = blockIdx.x * blockDim.x + threadIdx.x;
    if (i < N) {
        float x = scan[3 * i + 0];
        float y = scan[3 * i + 1];
        float z = scan[3 * i + 2];
        g_pack[i] = make_float4(-2.0f * x, -2.0f * y, -2.0f * z,
                                fmaf(x, x, fmaf(y, y, z * z)));
    }
    if (i < M) g_minbits[i] = 0x7FFFFFFF;  // +inf in ordered-int space
}

__global__ void __launch_bounds__(BLOCK)
chamfer_min_kernel(const float* __restrict__ tmpl, int N, int M) {
    __shared__ float4 tile[TILE];

    const int chunkSize = (N + SCAN_CHUNKS - 1) / SCAN_CHUNKS;
    const int s0 = blockIdx.x * chunkSize;
    const int s1 = min(s0 + chunkSize, N);

    const int base = blockIdx.y * (BLOCK * T_PER_THREAD) + threadIdx.x;

    float tx[T_PER_THREAD], ty[T_PER_THREAD], tz[T_PER_THREAD], mn[T_PER_THREAD];
#pragma unroll
    for (int t = 0; t < T_PER_THREAD; t++) {
        int m = base + t * BLOCK;
        int mc = m < M ? m : (M - 1);         // clamp; duplicates never atomically written
        tx[t] = __ldg(&tmpl[3 * mc + 0]);
        ty[t] = __ldg(&tmpl[3 * mc + 1]);
        tz[t] = __ldg(&tmpl[3 * mc + 2]);
        mn[t] = __int_as_float(0x7f800000);   // +inf
    }

    for (int t0 = s0; t0 < s1; t0 += TILE) {
        const int cnt = min(TILE, s1 - t0);
        __syncthreads();
        for (int i = threadIdx.x; i < cnt; i += BLOCK)
            tile[i] = g_pack[t0 + i];
        __syncthreads();

#pragma unroll 4
        for (int j = 0; j < cnt; j++) {
            const float4 s = tile[j];
#pragma unroll
            for (int t = 0; t < T_PER_THREAD; t++) {
                float acc = fmaf(tx[t], s.x, s.w);
                acc = fmaf(ty[t], s.y, acc);
                acc = fmaf(tz[t], s.z, acc);
                mn[t] = fminf(mn[t], acc);
            }
        }
    }

#pragma unroll
    for (int t = 0; t < T_PER_THREAD; t++) {
        int m = base + t * BLOCK;
        if (m < M) atomicMin(&g_minbits[m], f2ord(mn[t]));
    }
}

__global__ void reduce_kernel(const float* __restrict__ tmpl, int M,
                              float* __restrict__ out) {
    __shared__ float warpsum[32];
    float local = 0.0f;
    for (int m = threadIdx.x; m < M; m += blockDim.x) {
        float v = ord2f(g_minbits[m]);
        float x = tmpl[3 * m + 0];
        float y = tmpl[3 * m + 1];
        float z = tmpl[3 * m + 2];
        float d2 = v + fmaf(x, x, fmaf(y, y, z * z));
        if (d2 < 0.1f) local += d2;
    }
#pragma unroll
    for (int o = 16; o > 0; o >>= 1)
        local += __shfl_down_sync(0xFFFFFFFFu, local, o);
    if ((threadIdx.x & 31) == 0) warpsum[threadIdx.x >> 5] = local;
    __syncthreads();
    if (threadIdx.x < 32) {
        int nw = (blockDim.x + 31) >> 5;
        float v = (threadIdx.x < nw) ? warpsum[threadIdx.x] : 0.0f;
#pragma unroll
        for (int o = 16; o > 0; o >>= 1)
            v += __shfl_down_sync(0xFFFFFFFFu, v, o);
        if (threadIdx.x == 0) out[0] = v;
    }
}

extern "C" void kernel_launch(void* const* d_in, const int* in_sizes, int n_in,
                              void* d_out, int out_size) {
    const float* scan = (const float*)d_in[0];
    const float* tmpl = (const float*)d_in[1];
    const int N = in_sizes[0] / 3;
    const int M = in_sizes[1] / 3;

    int big = N > M ? N : M;
    pack_init_kernel<<<(big + 255) / 256, 256>>>(scan, N, M);

    dim3 grid(SCAN_CHUNKS, (M + BLOCK * T_PER_THREAD - 1) / (BLOCK * T_PER_THREAD));
    chamfer_min_kernel<<<grid, BLOCK>>>(tmpl, N, M);

    reduce_kernel<<<1, 1024>>>(tmpl, M, (float*)d_out);
}